// round 9
// baseline (speedup 1.0000x reference)
#include <cuda_runtime.h>
#include <cuda_fp16.h>
#include <cstdint>

// ============================================================================
// Problem constants
// ============================================================================
#define NN    8192
#define IN_F  256
#define F     128          // OUT_F
#define MT    64           // rows per CTA (gat kernel)
#define KC    128          // j-chunk
#define NCHH  32           // chunks per CTA (j-half split)
#define NF    136          // B rows: 128 features + ones row (128) + zero pad
#define USTRD 140          // partial-u row stride (floats)

// ============================================================================
// Scratch globals (no cudaMalloc) — 16B aligned for u32 / cp.async access
// ============================================================================
__device__ __align__(16) __half g_sh[NN];       // fp16(s)
__device__ __align__(16) float  g_e1[NN];       // exp(s)
__device__ __align__(16) float  g_e2[NN];       // exp(0.2 s)
__device__ __align__(16) __half g_ej1h[NN];     // fp16(exp(s))
__device__ __align__(16) __half g_ej2h[NN];     // fp16(exp(0.2 s))
__device__ __align__(16) __half g_Y[NF * NN];   // [f][j] fp16 Wh^T (+ones row)
__device__ __align__(16) float  g_u[2 * NN * USTRD];  // per-j-half partial u

// ============================================================================
// SMEM layout (gat): swizzled blocked tiles, double buffered, + adj ring
//   A tile: 64 r x 128 k f16, 2 k-blocks                -> 16384 B
//   Y tile: 136 r x 128 k f16, 2 k-blocks (stride 17408)-> 34816 B
//   adj tile: 64 r x 128 int, row stride 528 B          -> 33792 B
// ============================================================================
#define ABY   16384
#define YBY   34816
#define SA1(b) ((b) * ABY)              // 0 / 16384
#define SA2(b) (32768 + (b) * ABY)      // 32768 / 49152
#define SYB(b) (65536 + (b) * YBY)      // 65536 / 100352
#define SADJ(b) (135168 + (b) * 33792)  // 135168 / 168960
#define SMEM_TOT (135168 + 2 * 33792)   // 202752

// ============================================================================
// PTX helpers (base sm_100 legal)
// ============================================================================
__device__ __forceinline__ uint32_t smem_u32(const void* p) {
    uint32_t a;
    asm("{ .reg .u64 t; cvta.to.shared.u64 t, %1; cvt.u32.u64 %0, t; }"
        : "=r"(a) : "l"(p));
    return a;
}
__device__ __forceinline__ void ldsm4(uint32_t* r, uint32_t addr) {
    asm volatile("ldmatrix.sync.aligned.m8n8.x4.shared.b16 {%0,%1,%2,%3}, [%4];"
                 : "=r"(r[0]), "=r"(r[1]), "=r"(r[2]), "=r"(r[3]) : "r"(addr));
}
__device__ __forceinline__ void ldsm2(uint32_t* r, uint32_t addr) {
    asm volatile("ldmatrix.sync.aligned.m8n8.x2.shared.b16 {%0,%1}, [%2];"
                 : "=r"(r[0]), "=r"(r[1]) : "r"(addr));
}
__device__ __forceinline__ void mma16816(float* d, const uint32_t* a,
                                         uint32_t b0, uint32_t b1) {
    asm volatile(
        "mma.sync.aligned.m16n8k16.row.col.f32.f16.f16.f32 "
        "{%0,%1,%2,%3},{%4,%5,%6,%7},{%8,%9},{%0,%1,%2,%3};"
        : "+f"(d[0]), "+f"(d[1]), "+f"(d[2]), "+f"(d[3])
        : "r"(a[0]), "r"(a[1]), "r"(a[2]), "r"(a[3]), "r"(b0), "r"(b1));
}
__device__ __forceinline__ void cpasync16(uint32_t dst, const void* src) {
    asm volatile("cp.async.cg.shared.global [%0], [%1], 16;" :: "r"(dst), "l"(src)
                 : "memory");
}
__device__ __forceinline__ void cpasync_commit() {
    asm volatile("cp.async.commit_group;" ::: "memory");
}
__device__ __forceinline__ void cpasync_wait0() {
    asm volatile("cp.async.wait_group 0;" ::: "memory");
}
__device__ __forceinline__ void cpasync_wait1() {
    asm volatile("cp.async.wait_group 1;" ::: "memory");
}
__device__ __forceinline__ void cpasync_wait2() {
    asm volatile("cp.async.wait_group 2;" ::: "memory");
}
__device__ __forceinline__ uint32_t h2u(__half2 v) {
    union { __half2 h; uint32_t u; } x; x.h = v; return x.u;
}
__device__ __forceinline__ __half2 u2h(uint32_t v) {
    union { __half2 h; uint32_t u; } x; x.u = v; return x.h;
}

// ============================================================================
// Kernel 1 (fused prep) — unchanged, known-good
// ============================================================================
#define P_HS   0
#define P_WS   9216
#define P_WHS  (P_WS + 33280)
#define P_A    (P_WHS + 17024)
#define P_TOT  (P_A + 512)

__global__ __launch_bounds__(256) void prep_kernel(const float* __restrict__ h,
                                                   const float* __restrict__ W,
                                                   const float* __restrict__ a) {
    extern __shared__ char psm[];
    float* hs  = (float*)(psm + P_HS);
    float* Ws  = (float*)(psm + P_WS);
    float* whs = (float*)(psm + P_WHS);
    float* as_ = (float*)(psm + P_A);

    const int t  = threadIdx.x;
    const int i0 = blockIdx.x * 32;
    const int f  = t & 127;
    const int hf = t >> 7;

    if (t < 128) as_[t] = a[t];

    float acc[16];
#pragma unroll
    for (int i = 0; i < 16; i++) acc[i] = 0.f;

    for (int kb = 0; kb < IN_F; kb += 64) {
        __syncthreads();
        for (int idx = t; idx < 32 * 64; idx += 256) {
            int i = idx >> 6, kk = idx & 63;
            hs[kk * 36 + i] = h[(size_t)(i0 + i) * IN_F + kb + kk];
        }
        for (int idx = t; idx < 128 * 64; idx += 256) {
            int ff = idx >> 6, kk = idx & 63;
            Ws[ff * 65 + kk] = W[(size_t)ff * IN_F + kb + kk];
        }
        __syncthreads();
#pragma unroll 4
        for (int kk = 0; kk < 64; kk++) {
            float wv = Ws[f * 65 + kk];
            const float* hv = &hs[kk * 36 + hf * 16];
#pragma unroll
            for (int i = 0; i < 16; i += 4) {
                float4 v = *(const float4*)&hv[i];
                acc[i + 0] = fmaf(wv, v.x, acc[i + 0]);
                acc[i + 1] = fmaf(wv, v.y, acc[i + 1]);
                acc[i + 2] = fmaf(wv, v.z, acc[i + 2]);
                acc[i + 3] = fmaf(wv, v.w, acc[i + 3]);
            }
        }
    }
    __syncthreads();
#pragma unroll
    for (int i = 0; i < 16; i++)
        whs[(hf * 16 + i) * 133 + f] = acc[i];
    __syncthreads();

    {
        const int wid  = t >> 5;
        const int lane = t & 31;
#pragma unroll
        for (int r = 0; r < 4; r++) {
            int row = wid * 4 + r;
            float sum = 0.f;
#pragma unroll
            for (int m = 0; m < 4; m++)
                sum += whs[row * 133 + lane + 32 * m] * as_[lane + 32 * m];
#pragma unroll
            for (int off = 16; off; off >>= 1)
                sum += __shfl_xor_sync(0xffffffffu, sum, off);
            if (lane == 0) {
                float e1 = __expf(sum);
                float e2 = __expf(0.2f * sum);
                g_sh[i0 + row]   = __float2half(sum);
                g_e1[i0 + row]   = e1;
                g_e2[i0 + row]   = e2;
                g_ej1h[i0 + row] = __float2half(e1);
                g_ej2h[i0 + row] = __float2half(e2);
            }
        }
    }

    for (int idx = t; idx < NF * 32; idx += 256) {
        int ff = idx >> 5, i = idx & 31;
        float v = (ff < F) ? whs[i * 133 + ff] : (ff == F ? 1.0f : 0.0f);
        g_Y[(size_t)ff * NN + i0 + i] = __float2half(v);
    }
}

// ============================================================================
// Kernel 2 (main): dual masked GEMM; adj staged via 2-deep cp.async ring.
// grid = 256: bid&127 -> row tile, bid>>7 -> j half. 512 threads.
// ============================================================================
__global__ __launch_bounds__(512, 1) void gat_kernel(const int* __restrict__ adj) {
    extern __shared__ char smem[];
    const uint32_t sb = smem_u32(smem);

    const int t    = threadIdx.x;
    const int lane = t & 31;
    const int wid  = t >> 5;
    const int ms   = wid & 3;     // m slice (16 rows)
    const int nq   = wid >> 2;    // n quarter
    const int rt   = blockIdx.x & 127;
    const int jh   = blockIdx.x >> 7;
    const int i0   = rt * MT;
    const int jbase0 = jh * (NN / 2);

    const int NT = (nq == 3) ? 5 : 4;
    float acc1[5][4], acc2[5][4];
#pragma unroll
    for (int n = 0; n < 5; n++)
#pragma unroll
        for (int k = 0; k < 4; k++) { acc1[n][k] = 0.f; acc2[n][k] = 0.f; }

    // ---- build-phase indices: 8 threads/row, 16 j each ----
    const int brow = t >> 3;
    const int jq   = t & 7;
    const int jb8  = jq * 16;
    const int jbyte0 = jb8 * 2;
    const uint32_t bldoff = (uint32_t)(((jbyte0 >> 7) << 13) + brow * 128);
    const uint32_t bswx   = (uint32_t)((brow & 7) << 4);
    const uint32_t binner = (uint32_t)(jbyte0 & 127);
    const __half2 si2 = __half2half2(g_sh[i0 + brow]);
    const __half2 z2  = __float2half2_rn(0.f);

    // ---- mma-phase constants ----
    const uint32_t rA    = (uint32_t)(ms * 16 + (lane & 15));
    const uint32_t rAoff = rA * 128;
    const uint32_t swxA  = (rA & 7) << 4;
    const int khA = ((lane >> 4) & 1) * 8;
    const int khB = ((lane >> 3) & 1) * 8;
    uint32_t fOff[2], fSwx[2];
#pragma unroll
    for (int np = 0; np < 2; np++) {
        uint32_t fidx = (uint32_t)(nq * 32 + np * 16 + ((lane >> 4) & 1) * 8 + (lane & 7));
        fOff[np] = fidx * 128;
        fSwx[np] = (fidx & 7) << 4;
    }
    const uint32_t f3idx = (uint32_t)(128 + (lane & 7));
    const uint32_t f3Off = f3idx * 128;
    const uint32_t f3Swx = (f3idx & 7) << 4;

    auto stageY = [&](int jc, int bsel) {
        const uint32_t yb = sb + SYB(bsel);
        const char* ysrc = (const char*)g_Y + (size_t)jc * 2;
        for (int idx = t; idx < NF * 16; idx += 512) {
            int fr = idx >> 4, c = idx & 15;
            int blk = c >> 3, cc = c & 7;
            uint32_t dst = yb + blk * 17408 + fr * 128 + ((cc * 16) ^ ((fr & 7) << 4));
            cpasync16(dst, ysrc + (size_t)fr * (NN * 2) + c * 16);
        }
        cpasync_commit();
    };

    auto stageAdj = [&](int jc, int bsel) {
        const uint32_t ab = sb + SADJ(bsel);
        for (int idx = t; idx < 64 * 32; idx += 512) {
            int r = idx >> 5, c = idx & 31;
            cpasync16(ab + r * 528 + c * 16,
                      (const char*)(adj + (size_t)(i0 + r) * NN + jc) + c * 16);
        }
        cpasync_commit();
    };

    auto buildI = [&](int jc, int bsel) {
        const char* asrc = smem + SADJ(bsel) + brow * 528 + jq * 64;
        const uint32_t* sjp = (const uint32_t*)(g_sh   + jc + jb8);
        const uint32_t* e1p = (const uint32_t*)(g_ej1h + jc + jb8);
        const uint32_t* e2p = (const uint32_t*)(g_ej2h + jc + jb8);
        uint32_t a1w[8], a2w[8];
#pragma unroll
        for (int p = 0; p < 4; p++) {
            int4 v = *(const int4*)(asrc + p * 16);
            uint32_t m01 = __byte_perm((uint32_t)v.x, (uint32_t)v.y, 0x5410) * 0xFFFFu;
            uint32_t m23 = __byte_perm((uint32_t)v.z, (uint32_t)v.w, 0x5410) * 0xFFFFu;
            __half2 s0 = __hadd2(si2, u2h(__ldg(&sjp[2 * p])));
            __half2 s1 = __hadd2(si2, u2h(__ldg(&sjp[2 * p + 1])));
            __half2 g0 = __hgt2(s0, z2), g1 = __hgt2(s1, z2);
            __half2 c0 = __hle2(s0, z2), c1 = __hle2(s1, z2);
            a1w[2 * p]     = h2u(__hmul2(u2h(__ldg(&e1p[2 * p])),     g0)) & m01;
            a1w[2 * p + 1] = h2u(__hmul2(u2h(__ldg(&e1p[2 * p + 1])), g1)) & m23;
            a2w[2 * p]     = h2u(__hmul2(u2h(__ldg(&e2p[2 * p])),     c0)) & m01;
            a2w[2 * p + 1] = h2u(__hmul2(u2h(__ldg(&e2p[2 * p + 1])), c1)) & m23;
        }
        char* p1 = smem + SA1(bsel) + bldoff;
        char* p2 = smem + SA2(bsel) + bldoff;
#pragma unroll
        for (int qq = 0; qq < 2; qq++) {
            uint32_t o = (binner + 16 * qq) ^ bswx;
            *(uint4*)(p1 + o) = make_uint4(a1w[4 * qq], a1w[4 * qq + 1],
                                           a1w[4 * qq + 2], a1w[4 * qq + 3]);
            *(uint4*)(p2 + o) = make_uint4(a2w[4 * qq], a2w[4 * qq + 1],
                                           a2w[4 * qq + 2], a2w[4 * qq + 3]);
        }
    };

    auto mmaPhase = [&](int bsel) {
        const uint32_t a1b = sb + SA1(bsel) + rAoff;
        const uint32_t a2b = sb + SA2(bsel) + rAoff;
        const uint32_t yb  = sb + SYB(bsel);
#pragma unroll 1
        for (int ks = 0; ks < 8; ks++) {
            const int kA = ks * 16 + khA;
            const uint32_t aoff = ((uint32_t)(kA >> 6) << 13) + (((uint32_t)(kA & 63) * 2) ^ swxA);
            const int kB = ks * 16 + khB;
            const uint32_t bblk = (uint32_t)(kB >> 6) * 17408;
            const uint32_t bkin = (uint32_t)(kB & 63) * 2;
            uint32_t a1[4], a2[4], b[4];
            ldsm4(a1, a1b + aoff);
            ldsm4(a2, a2b + aoff);
#pragma unroll
            for (int np = 0; np < 2; np++) {
                ldsm4(b, yb + bblk + fOff[np] + (bkin ^ fSwx[np]));
                mma16816(acc1[2 * np],     a1, b[0], b[1]);
                mma16816(acc1[2 * np + 1], a1, b[2], b[3]);
                mma16816(acc2[2 * np],     a2, b[0], b[1]);
                mma16816(acc2[2 * np + 1], a2, b[2], b[3]);
            }
            if (nq == 3) {
                ldsm2(b, yb + bblk + f3Off + (bkin ^ f3Swx));
                mma16816(acc1[4], a1, b[0], b[1]);
                mma16816(acc2[4], a2, b[0], b[1]);
            }
        }
    };

    // ---- prologue: Y(0), adj(0), adj(1) in flight; build(0) ----
    stageY(jbase0, 0);                  // Gy0
    stageAdj(jbase0, 0);                // Ga0
    stageAdj(jbase0 + KC, 1);           // Ga1 (newest)
    cpasync_wait1();                    // Gy0 would be forced too.. order: Gy0,Ga0 done
    // NOTE: commit order was Y,adj0,adj1 -> wait1 leaves only Ga1 outstanding
    __syncthreads();
    buildI(jbase0, 0);
    __syncthreads();

    // ---- pipelined main loop ----
    for (int c = 0; c < NCHH; c++) {
        const int b = c & 1;
        const bool hasY  = (c + 1 < NCHH);
        const bool hasAj = (c + 2 < NCHH);
        if (hasY)  stageY(jbase0 + (c + 1) * KC, b ^ 1);   // Gy(c+1)
        if (hasAj) stageAdj(jbase0 + (c + 2) * KC, b);     // Ga(c+2) newest
        mmaPhase(b);
        if (hasAj) cpasync_wait2(); else cpasync_wait1();  // adj(c+1) complete
        if (hasY)  buildI(jbase0 + (c + 1) * KC, b ^ 1);
        if (hasAj) cpasync_wait1(); else cpasync_wait0();  // Y(c+1) complete
        __syncthreads();
    }

    // ---- write partial u = e1_i*D1 + e2_i*D2 ----
    {
        float* up = g_u + (size_t)jh * (NN * USTRD) + (size_t)i0 * USTRD;
        const int r0 = ms * 16 + (lane >> 2);
        const int r1 = r0 + 8;
        const float a10 = __ldg(&g_e1[i0 + r0]), a20 = __ldg(&g_e2[i0 + r0]);
        const float a11 = __ldg(&g_e1[i0 + r1]), a21 = __ldg(&g_e2[i0 + r1]);
        const int cb = nq * 32 + (lane & 3) * 2;
#pragma unroll
        for (int nt = 0; nt < 5; nt++) {
            if (nt >= NT) break;
            int col = cb + nt * 8;
            float2 v0, v1;
            v0.x = a10 * acc1[nt][0] + a20 * acc2[nt][0];
            v0.y = a10 * acc1[nt][1] + a20 * acc2[nt][1];
            v1.x = a11 * acc1[nt][2] + a21 * acc2[nt][2];
            v1.y = a11 * acc1[nt][3] + a21 * acc2[nt][3];
            *(float2*)&up[(size_t)r0 * USTRD + col] = v0;
            *(float2*)&up[(size_t)r1 * USTRD + col] = v1;
        }
    }
}

// ============================================================================
// Kernel 3: combine j-half partials, normalize, LayerNorm. warp/row.
// ============================================================================
__global__ __launch_bounds__(256) void combine_kernel(const float* __restrict__ gamma,
                                                      const float* __restrict__ beta,
                                                      float* __restrict__ out) {
    const int t    = threadIdx.x;
    const int lane = t & 31;
    const int wid  = t >> 5;
    const int row  = blockIdx.x * 8 + wid;

    const float* u0 = g_u + (size_t)row * USTRD;
    const float* u1 = g_u + (size_t)NN * USTRD + (size_t)row * USTRD;

    const float inv = 1.0f / (u0[128] + u1[128]);

    const int c4 = lane * 4;
    float4 p0 = *(const float4*)&u0[c4];
    float4 p1 = *(const float4*)&u1[c4];
    float4 v;
    v.x = (p0.x + p1.x) * inv;
    v.y = (p0.y + p1.y) * inv;
    v.z = (p0.z + p1.z) * inv;
    v.w = (p0.w + p1.w) * inv;

    float sm = v.x + v.y + v.z + v.w;
    float sq = v.x * v.x + v.y * v.y + v.z * v.z + v.w * v.w;
#pragma unroll
    for (int off = 16; off; off >>= 1) {
        sm += __shfl_xor_sync(0xffffffffu, sm, off);
        sq += __shfl_xor_sync(0xffffffffu, sq, off);
    }
    const float mean = sm * (1.0f / F);
    const float var  = sq * (1.0f / F) - mean * mean;
    const float rstd = rsqrtf(var + 1e-5f);

    float4 gm = *(const float4*)&gamma[c4];
    float4 bt = *(const float4*)&beta[c4];
    float4 o;
    o.x = (v.x - mean) * rstd * gm.x + bt.x;
    o.y = (v.y - mean) * rstd * gm.y + bt.y;
    o.z = (v.z - mean) * rstd * gm.z + bt.z;
    o.w = (v.w - mean) * rstd * gm.w + bt.w;
    *(float4*)&out[(size_t)row * F + c4] = o;
}

// ============================================================================
// Launch: inputs in metadata order: h, adj, W, a, gamma, beta
// ============================================================================
extern "C" void kernel_launch(void* const* d_in, const int* in_sizes, int n_in,
                              void* d_out, int out_size) {
    const float* h     = (const float*)d_in[0];
    const int*   adj   = (const int*)  d_in[1];
    const float* W     = (const float*)d_in[2];
    const float* a     = (const float*)d_in[3];
    const float* gamma = (const float*)d_in[4];
    const float* beta  = (const float*)d_in[5];
    float* out = (float*)d_out;

    cudaFuncSetAttribute(prep_kernel, cudaFuncAttributeMaxDynamicSharedMemorySize,
                         P_TOT);
    cudaFuncSetAttribute(gat_kernel, cudaFuncAttributeMaxDynamicSharedMemorySize,
                         SMEM_TOT);

    prep_kernel<<<NN / 32, 256, P_TOT>>>(h, W, a);
    gat_kernel<<<256, 512, SMEM_TOT>>>(adj);
    combine_kernel<<<NN / 8, 256>>>(gamma, beta, out);
}

// round 11
// speedup vs baseline: 1.0237x; 1.0237x over previous
#include <cuda_runtime.h>
#include <cuda_fp16.h>
#include <cstdint>

// ============================================================================
// Problem constants
// ============================================================================
#define NN    8192
#define IN_F  256
#define F     128          // OUT_F
#define MT    64           // rows per CTA (gat kernel)
#define KC    128          // j-chunk
#define NCHH  32           // chunks per CTA (j-half split)
#define NF    136          // B rows: 128 features + ones row (128) + zero pad
#define USTRD 140          // partial-u row stride (floats)

// ============================================================================
// Scratch globals (no cudaMalloc) — 16B aligned for u32 / cp.async access
// ============================================================================
__device__ __align__(16) __half g_sh[NN];       // fp16(s)
__device__ __align__(16) float  g_e1[NN];       // exp(s)
__device__ __align__(16) float  g_e2[NN];       // exp(0.2 s)
__device__ __align__(16) __half g_ej1h[NN];     // fp16(exp(s))
__device__ __align__(16) __half g_ej2h[NN];     // fp16(exp(0.2 s))
__device__ __align__(16) __half g_Y[NF * NN];   // [f][j] fp16 Wh^T (+ones row)
__device__ __align__(16) float  g_u[2 * NN * USTRD];  // per-j-half partial u

// ============================================================================
// SMEM layout (gat): swizzled blocked tiles, double buffered (R8 layout)
// ============================================================================
#define ABY   16384
#define YBY   34816
#define SA1(b) ((b) * ABY)              // 0 / 16384
#define SA2(b) (32768 + (b) * ABY)      // 32768 / 49152
#define SYB(b) (65536 + (b) * YBY)      // 65536 / 100352
#define SMEM_TOT (65536 + 2 * YBY)      // 135168

// ============================================================================
// PTX helpers (base sm_100 legal)
// ============================================================================
__device__ __forceinline__ uint32_t smem_u32(const void* p) {
    uint32_t a;
    asm("{ .reg .u64 t; cvta.to.shared.u64 t, %1; cvt.u32.u64 %0, t; }"
        : "=r"(a) : "l"(p));
    return a;
}
__device__ __forceinline__ void ldsm4(uint32_t* r, uint32_t addr) {
    asm volatile("ldmatrix.sync.aligned.m8n8.x4.shared.b16 {%0,%1,%2,%3}, [%4];"
                 : "=r"(r[0]), "=r"(r[1]), "=r"(r[2]), "=r"(r[3]) : "r"(addr));
}
__device__ __forceinline__ void ldsm2(uint32_t* r, uint32_t addr) {
    asm volatile("ldmatrix.sync.aligned.m8n8.x2.shared.b16 {%0,%1}, [%2];"
                 : "=r"(r[0]), "=r"(r[1]) : "r"(addr));
}
// fp16-accumulator HMMA (2x rate of f32-acc on the legacy mma.sync path)
__device__ __forceinline__ void mma16816h(uint32_t* d, const uint32_t* a,
                                          uint32_t b0, uint32_t b1) {
    asm volatile(
        "mma.sync.aligned.m16n8k16.row.col.f16.f16.f16.f16 "
        "{%0,%1},{%2,%3,%4,%5},{%6,%7},{%0,%1};"
        : "+r"(d[0]), "+r"(d[1])
        : "r"(a[0]), "r"(a[1]), "r"(a[2]), "r"(a[3]), "r"(b0), "r"(b1));
}
__device__ __forceinline__ void cpasync16(uint32_t dst, const void* src) {
    asm volatile("cp.async.cg.shared.global [%0], [%1], 16;" :: "r"(dst), "l"(src)
                 : "memory");
}
__device__ __forceinline__ void cpasync_commit() {
    asm volatile("cp.async.commit_group;" ::: "memory");
}
__device__ __forceinline__ void cpasync_wait0() {
    asm volatile("cp.async.wait_group 0;" ::: "memory");
}
__device__ __forceinline__ uint32_t h2u(__half2 v) {
    union { __half2 h; uint32_t u; } x; x.h = v; return x.u;
}
__device__ __forceinline__ __half2 u2h(uint32_t v) {
    union { __half2 h; uint32_t u; } x; x.u = v; return x.h;
}

// ============================================================================
// Kernel 1 (fused prep): Wh = h @ W^T ; s = Wh @ a^T ; scalars ; Y (transposed)
// ============================================================================
#define P_HS   0
#define P_WS   9216
#define P_WHS  (P_WS + 33280)
#define P_A    (P_WHS + 17024)
#define P_TOT  (P_A + 512)

__global__ __launch_bounds__(256) void prep_kernel(const float* __restrict__ h,
                                                   const float* __restrict__ W,
                                                   const float* __restrict__ a) {
    extern __shared__ char psm[];
    float* hs  = (float*)(psm + P_HS);
    float* Ws  = (float*)(psm + P_WS);
    float* whs = (float*)(psm + P_WHS);
    float* as_ = (float*)(psm + P_A);

    const int t  = threadIdx.x;
    const int i0 = blockIdx.x * 32;
    const int f  = t & 127;
    const int hf = t >> 7;

    if (t < 128) as_[t] = a[t];

    float acc[16];
#pragma unroll
    for (int i = 0; i < 16; i++) acc[i] = 0.f;

    for (int kb = 0; kb < IN_F; kb += 64) {
        __syncthreads();
        for (int idx = t; idx < 32 * 64; idx += 256) {
            int i = idx >> 6, kk = idx & 63;
            hs[kk * 36 + i] = h[(size_t)(i0 + i) * IN_F + kb + kk];
        }
        for (int idx = t; idx < 128 * 64; idx += 256) {
            int ff = idx >> 6, kk = idx & 63;
            Ws[ff * 65 + kk] = W[(size_t)ff * IN_F + kb + kk];
        }
        __syncthreads();
#pragma unroll 4
        for (int kk = 0; kk < 64; kk++) {
            float wv = Ws[f * 65 + kk];
            const float* hv = &hs[kk * 36 + hf * 16];
#pragma unroll
            for (int i = 0; i < 16; i += 4) {
                float4 v = *(const float4*)&hv[i];
                acc[i + 0] = fmaf(wv, v.x, acc[i + 0]);
                acc[i + 1] = fmaf(wv, v.y, acc[i + 1]);
                acc[i + 2] = fmaf(wv, v.z, acc[i + 2]);
                acc[i + 3] = fmaf(wv, v.w, acc[i + 3]);
            }
        }
    }
    __syncthreads();
#pragma unroll
    for (int i = 0; i < 16; i++)
        whs[(hf * 16 + i) * 133 + f] = acc[i];
    __syncthreads();

    {
        const int wid  = t >> 5;
        const int lane = t & 31;
#pragma unroll
        for (int r = 0; r < 4; r++) {
            int row = wid * 4 + r;
            float sum = 0.f;
#pragma unroll
            for (int m = 0; m < 4; m++)
                sum += whs[row * 133 + lane + 32 * m] * as_[lane + 32 * m];
#pragma unroll
            for (int off = 16; off; off >>= 1)
                sum += __shfl_xor_sync(0xffffffffu, sum, off);
            if (lane == 0) {
                float e1 = __expf(sum);
                float e2 = __expf(0.2f * sum);
                g_sh[i0 + row]   = __float2half(sum);
                g_e1[i0 + row]   = e1;
                g_e2[i0 + row]   = e2;
                g_ej1h[i0 + row] = __float2half(e1);
                g_ej2h[i0 + row] = __float2half(e2);
            }
        }
    }

    for (int idx = t; idx < NF * 32; idx += 256) {
        int ff = idx >> 5, i = idx & 31;
        float v = (ff < F) ? whs[i * 133 + ff] : (ff == F ? 1.0f : 0.0f);
        g_Y[(size_t)ff * NN + i0 + i] = __float2half(v);
    }
}

// ============================================================================
// Kernel 2 (main): dual masked GEMM on fp16-acc HMMA (per-chunk f32 promote).
// grid = 256: bid&127 -> row tile, bid>>7 -> j half. 512 threads.
// ============================================================================
__global__ __launch_bounds__(512, 1) void gat_kernel(const int* __restrict__ adj) {
    extern __shared__ char smem[];
    const uint32_t sb = smem_u32(smem);

    const int t    = threadIdx.x;
    const int lane = t & 31;
    const int wid  = t >> 5;
    const int ms   = wid & 3;     // m slice (16 rows)
    const int nq   = wid >> 2;    // n quarter
    const int rt   = blockIdx.x & 127;
    const int jh   = blockIdx.x >> 7;
    const int i0   = rt * MT;
    const int jbase0 = jh * (NN / 2);

    const int NT = (nq == 3) ? 5 : 4;
    float acc1[5][4], acc2[5][4];
#pragma unroll
    for (int n = 0; n < 5; n++)
#pragma unroll
        for (int k = 0; k < 4; k++) { acc1[n][k] = 0.f; acc2[n][k] = 0.f; }

    // ---- build-phase indices: 8 threads/row, 16 j each ----
    const int brow = t >> 3;
    const int jq   = t & 7;
    const int jb8  = jq * 16;
    const int jbyte0 = jb8 * 2;
    const uint32_t bldoff = (uint32_t)(((jbyte0 >> 7) << 13) + brow * 128);
    const uint32_t bswx   = (uint32_t)((brow & 7) << 4);
    const uint32_t binner = (uint32_t)(jbyte0 & 127);
    const __half2 si2 = __half2half2(g_sh[i0 + brow]);
    const __half2 z2  = __float2half2_rn(0.f);

    // ---- mma-phase constants ----
    const uint32_t rA    = (uint32_t)(ms * 16 + (lane & 15));
    const uint32_t rAoff = rA * 128;
    const uint32_t swxA  = (rA & 7) << 4;
    const int khA = ((lane >> 4) & 1) * 8;
    const int khB = ((lane >> 3) & 1) * 8;
    uint32_t fOff[2], fSwx[2];
#pragma unroll
    for (int np = 0; np < 2; np++) {
        uint32_t fidx = (uint32_t)(nq * 32 + np * 16 + ((lane >> 4) & 1) * 8 + (lane & 7));
        fOff[np] = fidx * 128;
        fSwx[np] = (fidx & 7) << 4;
    }
    const uint32_t f3idx = (uint32_t)(128 + (lane & 7));
    const uint32_t f3Off = f3idx * 128;
    const uint32_t f3Swx = (f3idx & 7) << 4;

    auto stageY = [&](int jc, int bsel) {
        const uint32_t yb = sb + SYB(bsel);
        const char* ysrc = (const char*)g_Y + (size_t)jc * 2;
        for (int idx = t; idx < NF * 16; idx += 512) {
            int fr = idx >> 4, c = idx & 15;
            int blk = c >> 3, cc = c & 7;
            uint32_t dst = yb + blk * 17408 + fr * 128 + ((cc * 16) ^ ((fr & 7) << 4));
            cpasync16(dst, ysrc + (size_t)fr * (NN * 2) + c * 16);
        }
        cpasync_commit();
    };

    auto buildI = [&](const int4* av, int jc, int bsel) {
        const uint32_t* sjp = (const uint32_t*)(g_sh   + jc + jb8);
        const uint32_t* e1p = (const uint32_t*)(g_ej1h + jc + jb8);
        const uint32_t* e2p = (const uint32_t*)(g_ej2h + jc + jb8);
        uint32_t a1w[8], a2w[8];
#pragma unroll
        for (int p = 0; p < 4; p++) {
            int4 v = av[p];
            uint32_t m01 = __byte_perm((uint32_t)v.x, (uint32_t)v.y, 0x5410) * 0xFFFFu;
            uint32_t m23 = __byte_perm((uint32_t)v.z, (uint32_t)v.w, 0x5410) * 0xFFFFu;
            __half2 s0 = __hadd2(si2, u2h(__ldg(&sjp[2 * p])));
            __half2 s1 = __hadd2(si2, u2h(__ldg(&sjp[2 * p + 1])));
            __half2 g0 = __hgt2(s0, z2), g1 = __hgt2(s1, z2);
            __half2 c0 = __hle2(s0, z2), c1 = __hle2(s1, z2);
            a1w[2 * p]     = h2u(__hmul2(u2h(__ldg(&e1p[2 * p])),     g0)) & m01;
            a1w[2 * p + 1] = h2u(__hmul2(u2h(__ldg(&e1p[2 * p + 1])), g1)) & m23;
            a2w[2 * p]     = h2u(__hmul2(u2h(__ldg(&e2p[2 * p])),     c0)) & m01;
            a2w[2 * p + 1] = h2u(__hmul2(u2h(__ldg(&e2p[2 * p + 1])), c1)) & m23;
        }
        char* p1 = smem + SA1(bsel) + bldoff;
        char* p2 = smem + SA2(bsel) + bldoff;
#pragma unroll
        for (int qq = 0; qq < 2; qq++) {
            uint32_t o = (binner + 16 * qq) ^ bswx;
            *(uint4*)(p1 + o) = make_uint4(a1w[4 * qq], a1w[4 * qq + 1],
                                           a1w[4 * qq + 2], a1w[4 * qq + 3]);
            *(uint4*)(p2 + o) = make_uint4(a2w[4 * qq], a2w[4 * qq + 1],
                                           a2w[4 * qq + 2], a2w[4 * qq + 3]);
        }
    };

    auto mmaPhase = [&](int bsel) {
        const uint32_t a1b = sb + SA1(bsel) + rAoff;
        const uint32_t a2b = sb + SA2(bsel) + rAoff;
        const uint32_t yb  = sb + SYB(bsel);
        // per-chunk fp16 accumulators (zeroed; promoted to f32 at chunk end)
        uint32_t h1[5][2], h2[5][2];
#pragma unroll
        for (int n = 0; n < 5; n++) {
            h1[n][0] = 0u; h1[n][1] = 0u; h2[n][0] = 0u; h2[n][1] = 0u;
        }
#pragma unroll 1
        for (int ks = 0; ks < 8; ks++) {
            const int kA = ks * 16 + khA;
            const uint32_t aoff = ((uint32_t)(kA >> 6) << 13) + (((uint32_t)(kA & 63) * 2) ^ swxA);
            const int kB = ks * 16 + khB;
            const uint32_t bblk = (uint32_t)(kB >> 6) * 17408;
            const uint32_t bkin = (uint32_t)(kB & 63) * 2;
            uint32_t a1[4], a2[4], b[4];
            ldsm4(a1, a1b + aoff);
            ldsm4(a2, a2b + aoff);
#pragma unroll
            for (int np = 0; np < 2; np++) {
                ldsm4(b, yb + bblk + fOff[np] + (bkin ^ fSwx[np]));
                mma16816h(h1[2 * np],     a1, b[0], b[1]);
                mma16816h(h1[2 * np + 1], a1, b[2], b[3]);
                mma16816h(h2[2 * np],     a2, b[0], b[1]);
                mma16816h(h2[2 * np + 1], a2, b[2], b[3]);
            }
            if (nq == 3) {
                ldsm2(b, yb + bblk + f3Off + (bkin ^ f3Swx));
                mma16816h(h1[4], a1, b[0], b[1]);
                mma16816h(h2[4], a2, b[0], b[1]);
            }
        }
        // promote chunk partials into fp32 accumulators
#pragma unroll
        for (int n = 0; n < 5; n++) {
            float2 v;
            v = __half22float2(u2h(h1[n][0])); acc1[n][0] += v.x; acc1[n][1] += v.y;
            v = __half22float2(u2h(h1[n][1])); acc1[n][2] += v.x; acc1[n][3] += v.y;
            v = __half22float2(u2h(h2[n][0])); acc2[n][0] += v.x; acc2[n][1] += v.y;
            v = __half22float2(u2h(h2[n][1])); acc2[n][2] += v.x; acc2[n][3] += v.y;
        }
    };

    // ---- prologue: chunk 0 ----
    {
        stageY(jbase0, 0);
        int4 av[4];
        const int4* ap = (const int4*)(adj + (size_t)(i0 + brow) * NN + jbase0 + jb8);
#pragma unroll
        for (int p = 0; p < 4; p++) av[p] = __ldg(&ap[p]);
        buildI(av, jbase0, 0);
        cpasync_wait0();
    }
    __syncthreads();

    // ---- pipelined main loop ----
    for (int c = 0; c < NCHH; c++) {
        const int b = c & 1;
        int4 av[4];
        const bool pf = (c + 1 < NCHH);
        const int jcn = jbase0 + (c + 1) * KC;
        if (pf) {
            const int4* ap = (const int4*)(adj + (size_t)(i0 + brow) * NN + jcn + jb8);
#pragma unroll
            for (int p = 0; p < 4; p++) av[p] = __ldg(&ap[p]);
            stageY(jcn, b ^ 1);
        }
        mmaPhase(b);
        if (pf) buildI(av, jcn, b ^ 1);
        cpasync_wait0();
        __syncthreads();
    }

    // ---- write partial u = e1_i*D1 + e2_i*D2 ----
    {
        float* up = g_u + (size_t)jh * (NN * USTRD) + (size_t)i0 * USTRD;
        const int r0 = ms * 16 + (lane >> 2);
        const int r1 = r0 + 8;
        const float a10 = __ldg(&g_e1[i0 + r0]), a20 = __ldg(&g_e2[i0 + r0]);
        const float a11 = __ldg(&g_e1[i0 + r1]), a21 = __ldg(&g_e2[i0 + r1]);
        const int cb = nq * 32 + (lane & 3) * 2;
#pragma unroll
        for (int nt = 0; nt < 5; nt++) {
            if (nt >= NT) break;
            int col = cb + nt * 8;
            float2 v0, v1;
            v0.x = a10 * acc1[nt][0] + a20 * acc2[nt][0];
            v0.y = a10 * acc1[nt][1] + a20 * acc2[nt][1];
            v1.x = a11 * acc1[nt][2] + a21 * acc2[nt][2];
            v1.y = a11 * acc1[nt][3] + a21 * acc2[nt][3];
            *(float2*)&up[(size_t)r0 * USTRD + col] = v0;
            *(float2*)&up[(size_t)r1 * USTRD + col] = v1;
        }
    }
}

// ============================================================================
// Kernel 3: combine j-half partials, normalize, LayerNorm. warp/row.
// ============================================================================
__global__ __launch_bounds__(256) void combine_kernel(const float* __restrict__ gamma,
                                                      const float* __restrict__ beta,
                                                      float* __restrict__ out) {
    const int t    = threadIdx.x;
    const int lane = t & 31;
    const int wid  = t >> 5;
    const int row  = blockIdx.x * 8 + wid;

    const float* u0 = g_u + (size_t)row * USTRD;
    const float* u1 = g_u + (size_t)NN * USTRD + (size_t)row * USTRD;

    const float inv = 1.0f / (u0[128] + u1[128]);

    const int c4 = lane * 4;
    float4 p0 = *(const float4*)&u0[c4];
    float4 p1 = *(const float4*)&u1[c4];
    float4 v;
    v.x = (p0.x + p1.x) * inv;
    v.y = (p0.y + p1.y) * inv;
    v.z = (p0.z + p1.z) * inv;
    v.w = (p0.w + p1.w) * inv;

    float sm = v.x + v.y + v.z + v.w;
    float sq = v.x * v.x + v.y * v.y + v.z * v.z + v.w * v.w;
#pragma unroll
    for (int off = 16; off; off >>= 1) {
        sm += __shfl_xor_sync(0xffffffffu, sm, off);
        sq += __shfl_xor_sync(0xffffffffu, sq, off);
    }
    const float mean = sm * (1.0f / F);
    const float var  = sq * (1.0f / F) - mean * mean;
    const float rstd = rsqrtf(var + 1e-5f);

    float4 gm = *(const float4*)&gamma[c4];
    float4 bt = *(const float4*)&beta[c4];
    float4 o;
    o.x = (v.x - mean) * rstd * gm.x + bt.x;
    o.y = (v.y - mean) * rstd * gm.y + bt.y;
    o.z = (v.z - mean) * rstd * gm.z + bt.z;
    o.w = (v.w - mean) * rstd * gm.w + bt.w;
    *(float4*)&out[(size_t)row * F + c4] = o;
}

// ============================================================================
// Launch: inputs in metadata order: h, adj, W, a, gamma, beta
// ============================================================================
extern "C" void kernel_launch(void* const* d_in, const int* in_sizes, int n_in,
                              void* d_out, int out_size) {
    const float* h     = (const float*)d_in[0];
    const int*   adj   = (const int*)  d_in[1];
    const float* W     = (const float*)d_in[2];
    const float* a     = (const float*)d_in[3];
    const float* gamma = (const float*)d_in[4];
    const float* beta  = (const float*)d_in[5];
    float* out = (float*)d_out;

    cudaFuncSetAttribute(prep_kernel, cudaFuncAttributeMaxDynamicSharedMemorySize,
                         P_TOT);
    cudaFuncSetAttribute(gat_kernel, cudaFuncAttributeMaxDynamicSharedMemorySize,
                         SMEM_TOT);

    prep_kernel<<<NN / 32, 256, P_TOT>>>(h, W, a);
    gat_kernel<<<256, 512, SMEM_TOT>>>(adj);
    combine_kernel<<<NN / 8, 256>>>(gamma, beta, out);
}

// round 12
// speedup vs baseline: 1.1305x; 1.1043x over previous
#include <cuda_runtime.h>
#include <cuda_fp16.h>
#include <cstdint>

// ============================================================================
// Problem constants
// ============================================================================
#define NN    8192
#define IN_F  256
#define F     128          // OUT_F
#define MT    64           // rows per CTA (gat kernel)
#define KC    128          // j-chunk
#define NCHH  32           // chunks per CTA (j-half split)
#define NF    136          // B rows: 128 features + ones row (128) + zero pad
#define USTRD 140          // partial-u row stride (floats)

// ============================================================================
// Scratch globals (no cudaMalloc) — 16B aligned
// ============================================================================
__device__ __align__(16) float  g_s[NN];        // fp32 s (for exact exp args)
__device__ __align__(16) __half g_Y[NF * NN];   // [f][j] fp16 Wh^T (+ones row)
__device__ __align__(16) float  g_u[2 * NN * USTRD];  // per-j-half partial u

// ============================================================================
// SMEM layout (gat): single A tile + Y tile, double buffered
//   A tile: 64 r x 128 k f16, 2 k-blocks of 8192 B     -> 16384 B
//   Y tile: 136 r x 128 k f16, 2 k-blocks stride 17408 -> 34816 B
// ============================================================================
#define ABY   16384
#define YBY   34816
#define SAB(b) ((b) * ABY)              // 0 / 16384
#define SYB(b) (32768 + (b) * YBY)      // 32768 / 67584
#define SMEM_TOT (32768 + 2 * YBY)      // 102400

// ============================================================================
// PTX helpers (base sm_100 legal)
// ============================================================================
__device__ __forceinline__ uint32_t smem_u32(const void* p) {
    uint32_t a;
    asm("{ .reg .u64 t; cvta.to.shared.u64 t, %1; cvt.u32.u64 %0, t; }"
        : "=r"(a) : "l"(p));
    return a;
}
__device__ __forceinline__ void ldsm4(uint32_t* r, uint32_t addr) {
    asm volatile("ldmatrix.sync.aligned.m8n8.x4.shared.b16 {%0,%1,%2,%3}, [%4];"
                 : "=r"(r[0]), "=r"(r[1]), "=r"(r[2]), "=r"(r[3]) : "r"(addr));
}
__device__ __forceinline__ void ldsm2(uint32_t* r, uint32_t addr) {
    asm volatile("ldmatrix.sync.aligned.m8n8.x2.shared.b16 {%0,%1}, [%2];"
                 : "=r"(r[0]), "=r"(r[1]) : "r"(addr));
}
// f32-accumulator HMMA
__device__ __forceinline__ void mma16816(float* d, const uint32_t* a,
                                         uint32_t b0, uint32_t b1) {
    asm volatile(
        "mma.sync.aligned.m16n8k16.row.col.f32.f16.f16.f32 "
        "{%0,%1,%2,%3},{%4,%5,%6,%7},{%8,%9},{%0,%1,%2,%3};"
        : "+f"(d[0]), "+f"(d[1]), "+f"(d[2]), "+f"(d[3])
        : "r"(a[0]), "r"(a[1]), "r"(a[2]), "r"(a[3]), "r"(b0), "r"(b1));
}
__device__ __forceinline__ void cpasync16(uint32_t dst, const void* src) {
    asm volatile("cp.async.cg.shared.global [%0], [%1], 16;" :: "r"(dst), "l"(src)
                 : "memory");
}
__device__ __forceinline__ void cpasync_commit() {
    asm volatile("cp.async.commit_group;" ::: "memory");
}
__device__ __forceinline__ void cpasync_wait0() {
    asm volatile("cp.async.wait_group 0;" ::: "memory");
}
__device__ __forceinline__ uint32_t h2u(__half2 v) {
    union { __half2 h; uint32_t u; } x; x.h = v; return x.u;
}
__device__ __forceinline__ float ex2f(float x) {
    float y;
    asm("ex2.approx.f32 %0, %1;" : "=f"(y) : "f"(x));
    return y;
}

// ============================================================================
// Kernel 1 (fused prep): Wh = h @ W^T ; s = Wh @ a^T (fp32) ; Y (transposed)
// ============================================================================
#define P_HS   0
#define P_WS   9216
#define P_WHS  (P_WS + 33280)
#define P_A    (P_WHS + 17024)
#define P_TOT  (P_A + 512)

__global__ __launch_bounds__(256) void prep_kernel(const float* __restrict__ h,
                                                   const float* __restrict__ W,
                                                   const float* __restrict__ a) {
    extern __shared__ char psm[];
    float* hs  = (float*)(psm + P_HS);
    float* Ws  = (float*)(psm + P_WS);
    float* whs = (float*)(psm + P_WHS);
    float* as_ = (float*)(psm + P_A);

    const int t  = threadIdx.x;
    const int i0 = blockIdx.x * 32;
    const int f  = t & 127;
    const int hf = t >> 7;

    if (t < 128) as_[t] = a[t];

    float acc[16];
#pragma unroll
    for (int i = 0; i < 16; i++) acc[i] = 0.f;

    for (int kb = 0; kb < IN_F; kb += 64) {
        __syncthreads();
        for (int idx = t; idx < 32 * 64; idx += 256) {
            int i = idx >> 6, kk = idx & 63;
            hs[kk * 36 + i] = h[(size_t)(i0 + i) * IN_F + kb + kk];
        }
        for (int idx = t; idx < 128 * 64; idx += 256) {
            int ff = idx >> 6, kk = idx & 63;
            Ws[ff * 65 + kk] = W[(size_t)ff * IN_F + kb + kk];
        }
        __syncthreads();
#pragma unroll 4
        for (int kk = 0; kk < 64; kk++) {
            float wv = Ws[f * 65 + kk];
            const float* hv = &hs[kk * 36 + hf * 16];
#pragma unroll
            for (int i = 0; i < 16; i += 4) {
                float4 v = *(const float4*)&hv[i];
                acc[i + 0] = fmaf(wv, v.x, acc[i + 0]);
                acc[i + 1] = fmaf(wv, v.y, acc[i + 1]);
                acc[i + 2] = fmaf(wv, v.z, acc[i + 2]);
                acc[i + 3] = fmaf(wv, v.w, acc[i + 3]);
            }
        }
    }
    __syncthreads();
#pragma unroll
    for (int i = 0; i < 16; i++)
        whs[(hf * 16 + i) * 133 + f] = acc[i];
    __syncthreads();

    {
        const int wid  = t >> 5;
        const int lane = t & 31;
#pragma unroll
        for (int r = 0; r < 4; r++) {
            int row = wid * 4 + r;
            float sum = 0.f;
#pragma unroll
            for (int m = 0; m < 4; m++)
                sum += whs[row * 133 + lane + 32 * m] * as_[lane + 32 * m];
#pragma unroll
            for (int off = 16; off; off >>= 1)
                sum += __shfl_xor_sync(0xffffffffu, sum, off);
            if (lane == 0) g_s[i0 + row] = sum;
        }
    }

    for (int idx = t; idx < NF * 32; idx += 256) {
        int ff = idx >> 5, i = idx & 31;
        float v = (ff < F) ? whs[i * 133 + ff] : (ff == F ? 1.0f : 0.0f);
        g_Y[(size_t)ff * NN + i0 + i] = __float2half(v);
    }
}

// ============================================================================
// Kernel 2 (main): SINGLE masked exp-GEMM.
//   A[i,j] = adj ? 2^( lrelu(s_i+s_j)*log2(e) - 6 ) : 0   (fp16; global 2^-6
//            scale cancels in softmax normalization)
//   D = A @ B  (B = [Wh^T ; ones-row]); col 128 = row sums (denominators)
// grid = 256: bid&127 -> row tile, bid>>7 -> j half. 512 threads.
// ============================================================================
__global__ __launch_bounds__(512, 1) void gat_kernel(const int* __restrict__ adj) {
    extern __shared__ char smem[];
    const uint32_t sb = smem_u32(smem);

    const int t    = threadIdx.x;
    const int lane = t & 31;
    const int wid  = t >> 5;
    const int ms   = wid & 3;     // m slice (16 rows)
    const int nq   = wid >> 2;    // n quarter
    const int rt   = blockIdx.x & 127;
    const int jh   = blockIdx.x >> 7;
    const int i0   = rt * MT;
    const int jbase0 = jh * (NN / 2);

    const int NT = (nq == 3) ? 5 : 4;
    float acc[5][4];
#pragma unroll
    for (int n = 0; n < 5; n++)
#pragma unroll
        for (int k = 0; k < 4; k++) acc[n][k] = 0.f;

    // ---- build-phase indices: 8 threads/row, 16 j each ----
    const int brow = t >> 3;
    const int jq   = t & 7;
    const int jb8  = jq * 16;
    const int jbyte0 = jb8 * 2;
    const uint32_t bldoff = (uint32_t)(((jbyte0 >> 7) << 13) + brow * 128);
    const uint32_t bswx   = (uint32_t)((brow & 7) << 4);
    const uint32_t binner = (uint32_t)(jbyte0 & 127);
    const float si = g_s[i0 + brow];

    // ---- mma-phase constants ----
    const uint32_t rA    = (uint32_t)(ms * 16 + (lane & 15));
    const uint32_t rAoff = rA * 128;
    const uint32_t swxA  = (rA & 7) << 4;
    const int khA = ((lane >> 4) & 1) * 8;
    const int khB = ((lane >> 3) & 1) * 8;
    uint32_t fOff[2], fSwx[2];
#pragma unroll
    for (int np = 0; np < 2; np++) {
        uint32_t fidx = (uint32_t)(nq * 32 + np * 16 + ((lane >> 4) & 1) * 8 + (lane & 7));
        fOff[np] = fidx * 128;
        fSwx[np] = (fidx & 7) << 4;
    }
    const uint32_t f3idx = (uint32_t)(128 + (lane & 7));
    const uint32_t f3Off = f3idx * 128;
    const uint32_t f3Swx = (f3idx & 7) << 4;

    auto stageY = [&](int jc, int bsel) {
        const uint32_t yb = sb + SYB(bsel);
        const char* ysrc = (const char*)g_Y + (size_t)jc * 2;
        for (int idx = t; idx < NF * 16; idx += 512) {
            int fr = idx >> 4, c = idx & 15;
            int blk = c >> 3, cc = c & 7;
            uint32_t dst = yb + blk * 17408 + fr * 128 + ((cc * 16) ^ ((fr & 7) << 4));
            cpasync16(dst, ysrc + (size_t)fr * (NN * 2) + c * 16);
        }
        cpasync_commit();
    };

    auto buildI = [&](const int4* av, int jc, int bsel) {
        const float4* sjp = (const float4*)(g_s + jc + jb8);
        uint32_t aw[8];
#pragma unroll
        for (int p = 0; p < 4; p++) {
            int4 v = av[p];
            uint32_t m01 = __byte_perm((uint32_t)v.x, (uint32_t)v.y, 0x5410) * 0xFFFFu;
            uint32_t m23 = __byte_perm((uint32_t)v.z, (uint32_t)v.w, 0x5410) * 0xFFFFu;
            float4 sj = __ldg(&sjp[p]);
            float e0 = si + sj.x, e1 = si + sj.y, e2 = si + sj.z, e3 = si + sj.w;
            float l0 = e0 > 0.f ? e0 : 0.2f * e0;
            float l1 = e1 > 0.f ? e1 : 0.2f * e1;
            float l2 = e2 > 0.f ? e2 : 0.2f * e2;
            float l3 = e3 > 0.f ? e3 : 0.2f * e3;
            float w0 = ex2f(fmaf(l0, 1.44269504f, -6.0f));
            float w1 = ex2f(fmaf(l1, 1.44269504f, -6.0f));
            float w2 = ex2f(fmaf(l2, 1.44269504f, -6.0f));
            float w3 = ex2f(fmaf(l3, 1.44269504f, -6.0f));
            aw[2 * p]     = h2u(__floats2half2_rn(w0, w1)) & m01;
            aw[2 * p + 1] = h2u(__floats2half2_rn(w2, w3)) & m23;
        }
        char* pd = smem + SAB(bsel) + bldoff;
#pragma unroll
        for (int qq = 0; qq < 2; qq++) {
            uint32_t o = (binner + 16 * qq) ^ bswx;
            *(uint4*)(pd + o) = make_uint4(aw[4 * qq], aw[4 * qq + 1],
                                           aw[4 * qq + 2], aw[4 * qq + 3]);
        }
    };

    auto mmaPhase = [&](int bsel) {
        const uint32_t ab = sb + SAB(bsel) + rAoff;
        const uint32_t yb = sb + SYB(bsel);
#pragma unroll 1
        for (int ks = 0; ks < 8; ks++) {
            const int kA = ks * 16 + khA;
            const uint32_t aoff = ((uint32_t)(kA >> 6) << 13) + (((uint32_t)(kA & 63) * 2) ^ swxA);
            const int kB = ks * 16 + khB;
            const uint32_t bblk = (uint32_t)(kB >> 6) * 17408;
            const uint32_t bkin = (uint32_t)(kB & 63) * 2;
            uint32_t a[4], b[4];
            ldsm4(a, ab + aoff);
#pragma unroll
            for (int np = 0; np < 2; np++) {
                ldsm4(b, yb + bblk + fOff[np] + (bkin ^ fSwx[np]));
                mma16816(acc[2 * np],     a, b[0], b[1]);
                mma16816(acc[2 * np + 1], a, b[2], b[3]);
            }
            if (nq == 3) {
                ldsm2(b, yb + bblk + f3Off + (bkin ^ f3Swx));
                mma16816(acc[4], a, b[0], b[1]);
            }
        }
    };

    // ---- prologue: chunk 0 ----
    {
        stageY(jbase0, 0);
        int4 av[4];
        const int4* ap = (const int4*)(adj + (size_t)(i0 + brow) * NN + jbase0 + jb8);
#pragma unroll
        for (int p = 0; p < 4; p++) av[p] = __ldg(&ap[p]);
        buildI(av, jbase0, 0);
        cpasync_wait0();
    }
    __syncthreads();

    // ---- pipelined main loop ----
    for (int c = 0; c < NCHH; c++) {
        const int b = c & 1;
        int4 av[4];
        const bool pf = (c + 1 < NCHH);
        const int jcn = jbase0 + (c + 1) * KC;
        if (pf) {
            const int4* ap = (const int4*)(adj + (size_t)(i0 + brow) * NN + jcn + jb8);
#pragma unroll
            for (int p = 0; p < 4; p++) av[p] = __ldg(&ap[p]);
            stageY(jcn, b ^ 1);
        }
        mmaPhase(b);
        if (pf) buildI(av, jcn, b ^ 1);
        cpasync_wait0();
        __syncthreads();
    }

    // ---- write partial u (raw; softmax scale cancels globally) ----
    {
        float* up = g_u + (size_t)jh * (NN * USTRD) + (size_t)i0 * USTRD;
        const int r0 = ms * 16 + (lane >> 2);
        const int r1 = r0 + 8;
        const int cb = nq * 32 + (lane & 3) * 2;
#pragma unroll
        for (int nt = 0; nt < 5; nt++) {
            if (nt >= NT) break;
            int col = cb + nt * 8;
            *(float2*)&up[(size_t)r0 * USTRD + col] = make_float2(acc[nt][0], acc[nt][1]);
            *(float2*)&up[(size_t)r1 * USTRD + col] = make_float2(acc[nt][2], acc[nt][3]);
        }
    }
}

// ============================================================================
// Kernel 3: combine j-half partials, normalize, LayerNorm. warp/row.
// ============================================================================
__global__ __launch_bounds__(256) void combine_kernel(const float* __restrict__ gamma,
                                                      const float* __restrict__ beta,
                                                      float* __restrict__ out) {
    const int t    = threadIdx.x;
    const int lane = t & 31;
    const int wid  = t >> 5;
    const int row  = blockIdx.x * 8 + wid;

    const float* u0 = g_u + (size_t)row * USTRD;
    const float* u1 = g_u + (size_t)NN * USTRD + (size_t)row * USTRD;

    const float inv = 1.0f / (u0[128] + u1[128]);

    const int c4 = lane * 4;
    float4 p0 = *(const float4*)&u0[c4];
    float4 p1 = *(const float4*)&u1[c4];
    float4 v;
    v.x = (p0.x + p1.x) * inv;
    v.y = (p0.y + p1.y) * inv;
    v.z = (p0.z + p1.z) * inv;
    v.w = (p0.w + p1.w) * inv;

    float sm = v.x + v.y + v.z + v.w;
    float sq = v.x * v.x + v.y * v.y + v.z * v.z + v.w * v.w;
#pragma unroll
    for (int off = 16; off; off >>= 1) {
        sm += __shfl_xor_sync(0xffffffffu, sm, off);
        sq += __shfl_xor_sync(0xffffffffu, sq, off);
    }
    const float mean = sm * (1.0f / F);
    const float var  = sq * (1.0f / F) - mean * mean;
    const float rstd = rsqrtf(var + 1e-5f);

    float4 gm = *(const float4*)&gamma[c4];
    float4 bt = *(const float4*)&beta[c4];
    float4 o;
    o.x = (v.x - mean) * rstd * gm.x + bt.x;
    o.y = (v.y - mean) * rstd * gm.y + bt.y;
    o.z = (v.z - mean) * rstd * gm.z + bt.z;
    o.w = (v.w - mean) * rstd * gm.w + bt.w;
    *(float4*)&out[(size_t)row * F + c4] = o;
}

// ============================================================================
// Launch: inputs in metadata order: h, adj, W, a, gamma, beta
// ============================================================================
extern "C" void kernel_launch(void* const* d_in, const int* in_sizes, int n_in,
                              void* d_out, int out_size) {
    const float* h     = (const float*)d_in[0];
    const int*   adj   = (const int*)  d_in[1];
    const float* W     = (const float*)d_in[2];
    const float* a     = (const float*)d_in[3];
    const float* gamma = (const float*)d_in[4];
    const float* beta  = (const float*)d_in[5];
    float* out = (float*)d_out;

    cudaFuncSetAttribute(prep_kernel, cudaFuncAttributeMaxDynamicSharedMemorySize,
                         P_TOT);
    cudaFuncSetAttribute(gat_kernel, cudaFuncAttributeMaxDynamicSharedMemorySize,
                         SMEM_TOT);

    prep_kernel<<<NN / 32, 256, P_TOT>>>(h, W, a);
    gat_kernel<<<256, 512, SMEM_TOT>>>(adj);
    combine_kernel<<<NN / 8, 256>>>(gamma, beta, out);
}